// round 10
// baseline (speedup 1.0000x reference)
#include <cuda_runtime.h>
#include <cstdint>

// L1LossWithPenalty — warp-specialized TMA pipeline (R7 geometry + overhead cuts).
// out = (1/N) * sum_i [ sum_c |pred[i,c]-tgt[i,c]| ] * penalty[argmax pred_i, argmax tgt_i]
// N = 1048576, C = 27.  226 MB streamed -> HBM-bound.
//
// R9 vs R8 (42.0us / 67.5%) and R7 (kernel 40.1us / 70.3%):
//  - back to the measured-best 2-blocks/SM, 128-row-tile shape (grid 296);
//    cross-block de-phasing smooths DRAM demand.
//  - 2 bulk copies per tile (one per array) instead of 4 chunks.
//  - empty barrier arrives: 4 (one per consumer warp, after __syncwarp).
//  - penalty table in static smem (scatter ~3-4 bank phases vs ~20 L1TEX
//    wavefronts per warp via __ldg).

#define C        27
#define ROWS     128                  // rows per tile (= consumer threads)
#define CONS     128                  // consumer threads (4 warps)
#define THREADS  160                  // + 1 producer warp
#define TILE_F   (ROWS * C)           // 3456 floats per array
#define TILE_B   (TILE_F * 4)         // 13824 bytes per array
#define STAGE_F  (2 * TILE_F)
#define STAGES   4
#define SMEM_BYTES (STAGES * STAGE_F * 4)   // 110592 B dynamic
#define GRID     296

__device__ double   g_acc;
__device__ unsigned g_count;

// ---- mbarrier / TMA-bulk primitives ----
#define MBARRIER_INIT(addr, cnt) \
    asm volatile("mbarrier.init.shared.b64 [%0], %1;" :: "r"(addr), "r"(cnt) : "memory")

#define MBARRIER_ARRIVE(addr) \
    asm volatile("mbarrier.arrive.release.cta.shared.b64 _, [%0];" :: "r"(addr) : "memory")

#define MBARRIER_EXPECT_TX(addr, bytes) \
    asm volatile("mbarrier.arrive.expect_tx.shared.b64 _, [%0], %1;" \
                 :: "r"(addr), "r"(bytes) : "memory")

#define MBARRIER_WAIT_PARITY(addr, parity) do {                                   \
    uint32_t _mbar = (addr); uint32_t _par = (parity); uint32_t _done;            \
    asm volatile("{\n\t.reg .pred p;\n\t"                                         \
        "mbarrier.try_wait.parity.acquire.cta.shared::cta.b64 p, [%1], %2;\n\t"   \
        "selp.b32 %0, 1, 0, p;\n\t}"                                              \
        : "=r"(_done) : "r"(_mbar), "r"(_par) : "memory");                        \
    if (!_done) {                                                                 \
        asm volatile("{\n\t.reg .pred P1;\n\t"                                    \
            "WL_%=:\n\t"                                                          \
            "mbarrier.try_wait.parity.acquire.cta.shared::cta.b64 P1, [%0], %1, 0x989680;\n\t" \
            "@P1 bra.uni WD_%=;\n\t"                                              \
            "bra.uni WL_%=;\n\t"                                                  \
            "WD_%=:\n\t}" :: "r"(_mbar), "r"(_par) : "memory");                   \
    }                                                                             \
} while (0)

#define MBARRIER_WAIT_PARITY_RELAXED(addr, parity) do {                           \
    uint32_t _mbar = (addr); uint32_t _par = (parity); uint32_t _done;            \
    asm volatile("{\n\t.reg .pred p;\n\t"                                         \
        "mbarrier.try_wait.parity.relaxed.cta.shared::cta.b64 p, [%1], %2, 0x989680;\n\t" \
        "selp.b32 %0, 1, 0, p;\n\t}"                                              \
        : "=r"(_done) : "r"(_mbar), "r"(_par) : "memory");                        \
    if (!_done) {                                                                 \
        asm volatile("{\n\t.reg .pred P1;\n\t"                                    \
            "WL_%=:\n\t"                                                          \
            "mbarrier.try_wait.parity.relaxed.cta.shared::cta.b64 P1, [%0], %1, 0x989680;\n\t" \
            "@P1 bra.uni WD_%=;\n\t"                                              \
            "bra.uni WL_%=;\n\t"                                                  \
            "WD_%=:\n\t}" :: "r"(_mbar), "r"(_par) : "memory");                   \
    }                                                                             \
} while (0)

__device__ __forceinline__ void tma_bulk_g2s(uint32_t smem_dst, const void* gmem_src,
                                             uint32_t bytes, uint32_t mbar) {
    asm volatile(
        "cp.async.bulk.shared::cluster.global.mbarrier::complete_tx::bytes "
        "[%0], [%1], %2, [%3];"
        :: "r"(smem_dst), "l"(gmem_src), "r"(bytes), "r"(mbar) : "memory");
}

__global__ __launch_bounds__(THREADS)
void l1pen_kernel(const float* __restrict__ pred,
                  const float* __restrict__ tgt,
                  const float* __restrict__ pen,
                  int nrows,
                  float* __restrict__ out)
{
    extern __shared__ float dynsm[];            // [STAGES][2][TILE_F]
    __shared__ alignas(16) unsigned long long mbars[2 * STAGES];
    __shared__ float s_pen[C * C];              // 2916 B static
    __shared__ float s_warp[CONS / 32];

    const int tid    = threadIdx.x;
    const int wid    = tid >> 5;
    const int nfull  = nrows / ROWS;            // 8192 full tiles for N=1M
    const int ntiles = (nrows + ROWS - 1) / ROWS;
    const int stride = gridDim.x;

    const uint32_t mb0 = (uint32_t)__cvta_generic_to_shared(mbars);
    auto full_addr  = [&](int s) { return mb0 + (uint32_t)(2 * s) * 8u; };
    auto empty_addr = [&](int s) { return mb0 + (uint32_t)(2 * s + 1) * 8u; };

    // Penalty table to shared (all warps help; done before first compute).
    for (int i = tid; i < C * C; i += THREADS)
        s_pen[i] = pen[i];

    if (tid == 0) {
        #pragma unroll
        for (int s = 0; s < STAGES; s++) {
            MBARRIER_INIT(full_addr(s), 1u);               // producer expect_tx arrive
            MBARRIER_INIT(empty_addr(s), (uint32_t)(CONS / 32)); // 1 arrive/consumer warp
        }
    }
    __syncthreads();

    float acc = 0.0f;

    if (wid == CONS / 32) {
        // -------- producer warp (lane 0 only) --------
        if ((tid & 31) == 0) {
            int s = 0, phase = 1;                // phase=1: first empty-wait passes
            for (int tile = blockIdx.x; tile < nfull; tile += stride) {
                MBARRIER_WAIT_PARITY_RELAXED(empty_addr(s), phase);
                MBARRIER_EXPECT_TX(full_addr(s), 2u * TILE_B);
                const uint32_t dst =
                    (uint32_t)__cvta_generic_to_shared(dynsm + s * STAGE_F);
                tma_bulk_g2s(dst,          pred + (long)tile * TILE_F, TILE_B, full_addr(s));
                tma_bulk_g2s(dst + TILE_B, tgt  + (long)tile * TILE_F, TILE_B, full_addr(s));
                if (++s == STAGES) { s = 0; phase ^= 1; }
            }
        }
    } else {
        // -------- consumer warps (128 threads, 1 row each per tile) --------
        int s = 0, phase = 0;
        for (int tile = blockIdx.x; tile < ntiles; tile += stride) {
            if (tile < nfull) {
                MBARRIER_WAIT_PARITY(full_addr(s), phase);   // acquire: TMA data visible
                const float* __restrict__ pr = dynsm + s * STAGE_F + tid * C;
                const float* __restrict__ tr = pr + TILE_F;
                float l1 = 0.0f;
                float pmax = pr[0], tmax = tr[0];
                int   pidx = 0,     tidx = 0;
                #pragma unroll
                for (int c = 0; c < C; c++) {
                    float a = pr[c];
                    float b = tr[c];
                    l1 += fabsf(a - b);
                    if (a > pmax) { pmax = a; pidx = c; }   // strict > == jnp.argmax ties
                    if (b > tmax) { tmax = b; tidx = c; }
                }
                acc += l1 * s_pen[pidx * C + tidx];
                __syncwarp();                                // all lanes' reads done
                if ((tid & 31) == 0)
                    MBARRIER_ARRIVE(empty_addr(s));          // release, 1 per warp
                if (++s == STAGES) { s = 0; phase ^= 1; }
            } else {
                // ragged last tile (dead for N=1M): direct global reads
                const int rows = nrows - nfull * ROWS;
                if (tid < rows) {
                    const long base = (long)(nfull * ROWS + tid) * C;
                    float l1 = 0.0f;
                    float pmax = pred[base], tmax = tgt[base];
                    int   pidx = 0,          tidx = 0;
                    #pragma unroll
                    for (int c = 0; c < C; c++) {
                        float a = pred[base + c];
                        float b = tgt [base + c];
                        l1 += fabsf(a - b);
                        if (a > pmax) { pmax = a; pidx = c; }
                        if (b > tmax) { tmax = b; tidx = c; }
                    }
                    acc += l1 * s_pen[pidx * C + tidx];
                }
            }
        }

        // warp reduce (consumer warps only)
        #pragma unroll
        for (int off = 16; off > 0; off >>= 1)
            acc += __shfl_down_sync(0xffffffffu, acc, off);
        if ((tid & 31) == 0)
            s_warp[wid] = acc;
    }

    __syncthreads();   // all 5 warps: consumers done writing s_warp

    if (tid == 0) {
        float s = 0.0f;
        #pragma unroll
        for (int w = 0; w < CONS / 32; w++)
            s += s_warp[w];

        atomicAdd(&g_acc, (double)s);
        __threadfence();
        unsigned done = atomicAdd(&g_count, 1u) + 1u;
        if (done == gridDim.x) {
            __threadfence();
            double v = atomicAdd(&g_acc, 0.0);
            *out = (float)(v / (double)nrows);
            g_acc = 0.0;              // self-reset for next graph replay
            __threadfence();
            g_count = 0u;
        }
    }
}

extern "C" void kernel_launch(void* const* d_in, const int* in_sizes, int n_in,
                              void* d_out, int out_size)
{
    int pen_i = -1;
    for (int i = 0; i < n_in; i++)
        if (in_sizes[i] == C * C) { pen_i = i; break; }
    int big[2], nb = 0;
    for (int i = 0; i < n_in && nb < 2; i++)
        if (i != pen_i) big[nb++] = i;

    const float* pred = (const float*)d_in[big[0]];
    const float* tgt  = (const float*)d_in[big[1]];
    const float* pen  = (const float*)d_in[pen_i];

    const int nrows = in_sizes[big[0]] / C;

    cudaFuncSetAttribute(l1pen_kernel,
                         cudaFuncAttributeMaxDynamicSharedMemorySize, SMEM_BYTES);

    l1pen_kernel<<<GRID, THREADS, SMEM_BYTES>>>(pred, tgt, pen, nrows,
                                                (float*)d_out);
}